// round 1
// baseline (speedup 1.0000x reference)
#include <cuda_runtime.h>
#include <cuda_bf16.h>
#include <cstdint>

// Problem constants (GraphConvolution_5746666242438)
//   x        : [40000, 512] f32
//   weight   : [128, 512]   f32
//   bias     : [128]        f32
//   alpha    : [1]          f32
//   edge_val : [640000]     f32
//   edge_row : [640000]     i32
//   edge_col : [640000]     i32
// out: [40000, 128] f32

#define D_IN   512
#define D_OUT  128
#define MAX_NODES 40000

// Scratch for seq = X @ W^T  (40000 x 128 f32 = 20.48 MB)
__device__ float g_seq[(size_t)MAX_NODES * D_OUT];

// ---------------------------------------------------------------------------
// SGEMM: seq[M,128] = X[M,512] * W^T (W is [128,512] row-major)
// Block tile 128x128, BK=8, 256 threads, 8x8 per thread.
// ---------------------------------------------------------------------------
#define BM 128
#define BN 128
#define BK 8
#define TM 8
#define TN 8

__global__ __launch_bounds__(256) void sgemm_kernel(
    const float* __restrict__ X, const float* __restrict__ W,
    float* __restrict__ seq, int M)
{
    __shared__ float As[BK][BM];
    __shared__ float Bs[BK][BN];

    const int tid = threadIdx.x;
    const int block_m = blockIdx.x * BM;

    const int tm = (tid / 16) * TM;   // 0..120
    const int tn = (tid % 16) * TN;   // 0..120

    // Load indices: 256 threads each load 4 floats of A and 4 of B per k-chunk
    const int a_m  = tid >> 1;          // 0..127
    const int a_k4 = (tid & 1) * 4;     // 0 or 4
    const int b_n  = tid >> 1;          // 0..127 (row of W = output col)
    const int b_k4 = (tid & 1) * 4;

    float acc[TM][TN];
#pragma unroll
    for (int i = 0; i < TM; i++)
#pragma unroll
        for (int j = 0; j < TN; j++) acc[i][j] = 0.f;

    const int gm_a = block_m + a_m;
    const bool a_ok = (gm_a < M);

    for (int k0 = 0; k0 < D_IN; k0 += BK) {
        float4 av = make_float4(0.f, 0.f, 0.f, 0.f);
        if (a_ok)
            av = *reinterpret_cast<const float4*>(X + (size_t)gm_a * D_IN + k0 + a_k4);
        As[a_k4 + 0][a_m] = av.x;
        As[a_k4 + 1][a_m] = av.y;
        As[a_k4 + 2][a_m] = av.z;
        As[a_k4 + 3][a_m] = av.w;

        float4 bv = *reinterpret_cast<const float4*>(W + (size_t)b_n * D_IN + k0 + b_k4);
        Bs[b_k4 + 0][b_n] = bv.x;
        Bs[b_k4 + 1][b_n] = bv.y;
        Bs[b_k4 + 2][b_n] = bv.z;
        Bs[b_k4 + 3][b_n] = bv.w;

        __syncthreads();

#pragma unroll
        for (int k = 0; k < BK; k++) {
            float ra[TM], rb[TN];
#pragma unroll
            for (int i = 0; i < TM; i += 4) {
                float4 v = *reinterpret_cast<const float4*>(&As[k][tm + i]);
                ra[i] = v.x; ra[i+1] = v.y; ra[i+2] = v.z; ra[i+3] = v.w;
            }
#pragma unroll
            for (int j = 0; j < TN; j += 4) {
                float4 v = *reinterpret_cast<const float4*>(&Bs[k][tn + j]);
                rb[j] = v.x; rb[j+1] = v.y; rb[j+2] = v.z; rb[j+3] = v.w;
            }
#pragma unroll
            for (int i = 0; i < TM; i++)
#pragma unroll
                for (int j = 0; j < TN; j++)
                    acc[i][j] = fmaf(ra[i], rb[j], acc[i][j]);
        }
        __syncthreads();
    }

    // Store 8x8 tile
#pragma unroll
    for (int i = 0; i < TM; i++) {
        int gm = block_m + tm + i;
        if (gm < M) {
#pragma unroll
            for (int j = 0; j < TN; j += 4) {
                float4 v = make_float4(acc[i][j], acc[i][j+1], acc[i][j+2], acc[i][j+3]);
                *reinterpret_cast<float4*>(seq + (size_t)gm * D_OUT + tn + j) = v;
            }
        }
    }
}

// ---------------------------------------------------------------------------
// Zero out (d_out is poisoned)
// ---------------------------------------------------------------------------
__global__ void zero_kernel(float4* __restrict__ out, int n4)
{
    int i = blockIdx.x * blockDim.x + threadIdx.x;
    if (i < n4) out[i] = make_float4(0.f, 0.f, 0.f, 0.f);
}

// ---------------------------------------------------------------------------
// COO scatter: out[row] += val * seq[col]   (one warp per edge)
// ---------------------------------------------------------------------------
__global__ __launch_bounds__(256) void scatter_kernel(
    const float* __restrict__ seq,
    const float* __restrict__ edge_val,
    const int*   __restrict__ edge_row,
    const int*   __restrict__ edge_col,
    float* __restrict__ out, int E)
{
    int e = blockIdx.x * (blockDim.x >> 5) + (threadIdx.x >> 5);
    if (e >= E) return;
    const int lane = threadIdx.x & 31;

    const int   c = edge_col[e];
    const int   r = edge_row[e];
    const float v = edge_val[e];

    float4 s = *reinterpret_cast<const float4*>(seq + (size_t)c * D_OUT + lane * 4);
    float* o = out + (size_t)r * D_OUT + lane * 4;
    atomicAdd(o + 0, v * s.x);
    atomicAdd(o + 1, v * s.y);
    atomicAdd(o + 2, v * s.z);
    atomicAdd(o + 3, v * s.w);
}

// ---------------------------------------------------------------------------
// Epilogue: out = PReLU(out + bias)
// ---------------------------------------------------------------------------
__global__ void bias_prelu_kernel(float* __restrict__ out,
                                  const float* __restrict__ bias,
                                  const float* __restrict__ alpha, int n4)
{
    int i = blockIdx.x * blockDim.x + threadIdx.x;
    if (i >= n4) return;
    const float a = alpha[0];
    float4 v = reinterpret_cast<float4*>(out)[i];
    const int d = (i * 4) & (D_OUT - 1);
    float4 b = *reinterpret_cast<const float4*>(bias + d);
    v.x += b.x; v.y += b.y; v.z += b.z; v.w += b.w;
    v.x = v.x > 0.f ? v.x : a * v.x;
    v.y = v.y > 0.f ? v.y : a * v.y;
    v.z = v.z > 0.f ? v.z : a * v.z;
    v.w = v.w > 0.f ? v.w : a * v.w;
    reinterpret_cast<float4*>(out)[i] = v;
}

// ---------------------------------------------------------------------------
extern "C" void kernel_launch(void* const* d_in, const int* in_sizes, int n_in,
                              void* d_out, int out_size)
{
    const float* x        = (const float*)d_in[0];
    const float* weight   = (const float*)d_in[1];
    const float* bias     = (const float*)d_in[2];
    const float* alpha    = (const float*)d_in[3];
    const float* edge_val = (const float*)d_in[4];
    const int*   edge_row = (const int*)d_in[5];
    const int*   edge_col = (const int*)d_in[6];
    float*       out      = (float*)d_out;

    const int n_nodes = in_sizes[0] / D_IN;     // 40000
    const int n_edges = in_sizes[4];            // 640000

    float* seq = nullptr;
    cudaGetSymbolAddress((void**)&seq, g_seq);

    // 1) seq = X @ W^T
    {
        int grid = (n_nodes + BM - 1) / BM;
        sgemm_kernel<<<grid, 256>>>(x, weight, seq, n_nodes);
    }

    // 2) zero out
    {
        int n4 = out_size / 4;
        int grid = (n4 + 255) / 256;
        zero_kernel<<<grid, 256>>>((float4*)out, n4);
    }

    // 3) COO scatter with atomics
    {
        int edges_per_block = 256 / 32;
        int grid = (n_edges + edges_per_block - 1) / edges_per_block;
        scatter_kernel<<<grid, 256>>>(seq, edge_val, edge_row, edge_col, out, n_edges);
    }

    // 4) bias + PReLU
    {
        int n4 = out_size / 4;
        int grid = (n4 + 255) / 256;
        bias_prelu_kernel<<<grid, 256>>>(out, bias, alpha, n4);
    }
}

// round 2
// speedup vs baseline: 1.2062x; 1.2062x over previous
#include <cuda_runtime.h>
#include <cuda_bf16.h>
#include <cstdint>

// GraphConvolution: out = PReLU( A_coo @ (X @ W^T) + bias )
//   x        : [40000, 512] f32
//   weight   : [128, 512]   f32
//   bias     : [128]        f32
//   alpha    : [1]          f32
//   edge_val : [640000]     f32
//   edge_row : [640000]     i32
//   edge_col : [640000]     i32
// out: [40000, 128] f32

#define D_IN   512
#define D_OUT  128
#define MAX_NODES 40000
#define MAX_EDGES 640000

// Scratch (device globals: allocation-free rule)
__device__ float g_seq[(size_t)MAX_NODES * D_OUT];     // 20.48 MB
__device__ int   g_counts[MAX_NODES];
__device__ int   g_row_start[MAX_NODES + 1];
__device__ int   g_cursor[MAX_NODES];
__device__ int   g_sorted_col[MAX_EDGES];
__device__ float g_sorted_val[MAX_EDGES];

// ---------------------------------------------------------------------------
// SGEMM: seq[M,128] = X[M,512] * W^T (W is [128,512] row-major)
// ---------------------------------------------------------------------------
#define BM 128
#define BN 128
#define BK 8
#define TM 8
#define TN 8

__global__ __launch_bounds__(256) void sgemm_kernel(
    const float* __restrict__ X, const float* __restrict__ W,
    float* __restrict__ seq, int M)
{
    __shared__ float As[BK][BM];
    __shared__ float Bs[BK][BN];

    const int tid = threadIdx.x;
    const int block_m = blockIdx.x * BM;

    const int tm = (tid / 16) * TM;
    const int tn = (tid % 16) * TN;

    const int a_m  = tid >> 1;
    const int a_k4 = (tid & 1) * 4;
    const int b_n  = tid >> 1;
    const int b_k4 = (tid & 1) * 4;

    float acc[TM][TN];
#pragma unroll
    for (int i = 0; i < TM; i++)
#pragma unroll
        for (int j = 0; j < TN; j++) acc[i][j] = 0.f;

    const int gm_a = block_m + a_m;
    const bool a_ok = (gm_a < M);

    for (int k0 = 0; k0 < D_IN; k0 += BK) {
        float4 av = make_float4(0.f, 0.f, 0.f, 0.f);
        if (a_ok)
            av = *reinterpret_cast<const float4*>(X + (size_t)gm_a * D_IN + k0 + a_k4);
        As[a_k4 + 0][a_m] = av.x;
        As[a_k4 + 1][a_m] = av.y;
        As[a_k4 + 2][a_m] = av.z;
        As[a_k4 + 3][a_m] = av.w;

        float4 bv = *reinterpret_cast<const float4*>(W + (size_t)b_n * D_IN + k0 + b_k4);
        Bs[b_k4 + 0][b_n] = bv.x;
        Bs[b_k4 + 1][b_n] = bv.y;
        Bs[b_k4 + 2][b_n] = bv.z;
        Bs[b_k4 + 3][b_n] = bv.w;

        __syncthreads();

#pragma unroll
        for (int k = 0; k < BK; k++) {
            float ra[TM], rb[TN];
#pragma unroll
            for (int i = 0; i < TM; i += 4) {
                float4 v = *reinterpret_cast<const float4*>(&As[k][tm + i]);
                ra[i] = v.x; ra[i+1] = v.y; ra[i+2] = v.z; ra[i+3] = v.w;
            }
#pragma unroll
            for (int j = 0; j < TN; j += 4) {
                float4 v = *reinterpret_cast<const float4*>(&Bs[k][tn + j]);
                rb[j] = v.x; rb[j+1] = v.y; rb[j+2] = v.z; rb[j+3] = v.w;
            }
#pragma unroll
            for (int i = 0; i < TM; i++)
#pragma unroll
                for (int j = 0; j < TN; j++)
                    acc[i][j] = fmaf(ra[i], rb[j], acc[i][j]);
        }
        __syncthreads();
    }

#pragma unroll
    for (int i = 0; i < TM; i++) {
        int gm = block_m + tm + i;
        if (gm < M) {
#pragma unroll
            for (int j = 0; j < TN; j += 4) {
                float4 v = make_float4(acc[i][j], acc[i][j+1], acc[i][j+2], acc[i][j+3]);
                *reinterpret_cast<float4*>(seq + (size_t)gm * D_OUT + tn + j) = v;
            }
        }
    }
}

// ---------------------------------------------------------------------------
// CSR build: histogram -> scan -> bucket scatter
// ---------------------------------------------------------------------------
__global__ void zero_counts_kernel(int n)
{
    int i = blockIdx.x * blockDim.x + threadIdx.x;
    if (i < n) g_counts[i] = 0;
}

__global__ void hist_kernel(const int* __restrict__ edge_row, int E)
{
    int i = blockIdx.x * blockDim.x + threadIdx.x;
    if (i < E) atomicAdd(&g_counts[edge_row[i]], 1);
}

// Single block, 1024 threads: exclusive scan over n counts
__global__ __launch_bounds__(1024) void scan_kernel(int n)
{
    __shared__ int ssum[1024];
    const int tid = threadIdx.x;
    const int chunk = (n + 1023) / 1024;
    const int base = tid * chunk;

    int s = 0;
    for (int i = 0; i < chunk; i++) {
        int idx = base + i;
        if (idx < n) s += g_counts[idx];
    }
    ssum[tid] = s;
    __syncthreads();

    // Hillis-Steele inclusive scan
    for (int off = 1; off < 1024; off <<= 1) {
        int v = (tid >= off) ? ssum[tid - off] : 0;
        __syncthreads();
        ssum[tid] += v;
        __syncthreads();
    }

    int running = ssum[tid] - s;   // exclusive prefix for this thread's chunk
    for (int i = 0; i < chunk; i++) {
        int idx = base + i;
        if (idx < n) {
            g_row_start[idx] = running;
            g_cursor[idx]    = running;
            running += g_counts[idx];
        }
    }
    if (tid == 1023) g_row_start[n] = running;
}

__global__ void bucket_kernel(const float* __restrict__ edge_val,
                              const int*   __restrict__ edge_row,
                              const int*   __restrict__ edge_col, int E)
{
    int i = blockIdx.x * blockDim.x + threadIdx.x;
    if (i >= E) return;
    int r = edge_row[i];
    int pos = atomicAdd(&g_cursor[r], 1);
    g_sorted_col[pos] = edge_col[i];
    g_sorted_val[pos] = edge_val[i];
}

// ---------------------------------------------------------------------------
// Gather: one warp per row; fused bias + PReLU. Writes out exactly once.
// ---------------------------------------------------------------------------
__global__ __launch_bounds__(256) void gather_kernel(
    const float* __restrict__ seq,
    const float* __restrict__ bias,
    const float* __restrict__ alpha,
    float* __restrict__ out, int n_nodes)
{
    int w = blockIdx.x * (blockDim.x >> 5) + (threadIdx.x >> 5);
    if (w >= n_nodes) return;
    const int lane = threadIdx.x & 31;

    const int s = g_row_start[w];
    const int e = g_row_start[w + 1];

    float4 acc = make_float4(0.f, 0.f, 0.f, 0.f);
    for (int i = s; i < e; i++) {
        int   c = g_sorted_col[i];
        float v = g_sorted_val[i];
        float4 sv = *reinterpret_cast<const float4*>(seq + (size_t)c * D_OUT + lane * 4);
        acc.x = fmaf(v, sv.x, acc.x);
        acc.y = fmaf(v, sv.y, acc.y);
        acc.z = fmaf(v, sv.z, acc.z);
        acc.w = fmaf(v, sv.w, acc.w);
    }

    const float a = alpha[0];
    float4 b = *reinterpret_cast<const float4*>(bias + lane * 4);
    acc.x += b.x; acc.y += b.y; acc.z += b.z; acc.w += b.w;
    acc.x = acc.x > 0.f ? acc.x : a * acc.x;
    acc.y = acc.y > 0.f ? acc.y : a * acc.y;
    acc.z = acc.z > 0.f ? acc.z : a * acc.z;
    acc.w = acc.w > 0.f ? acc.w : a * acc.w;

    *reinterpret_cast<float4*>(out + (size_t)w * D_OUT + lane * 4) = acc;
}

// ---------------------------------------------------------------------------
extern "C" void kernel_launch(void* const* d_in, const int* in_sizes, int n_in,
                              void* d_out, int out_size)
{
    const float* x        = (const float*)d_in[0];
    const float* weight   = (const float*)d_in[1];
    const float* bias     = (const float*)d_in[2];
    const float* alpha    = (const float*)d_in[3];
    const float* edge_val = (const float*)d_in[4];
    const int*   edge_row = (const int*)d_in[5];
    const int*   edge_col = (const int*)d_in[6];
    float*       out      = (float*)d_out;

    const int n_nodes = in_sizes[0] / D_IN;     // 40000
    const int n_edges = in_sizes[4];            // 640000

    float* seq = nullptr;
    cudaGetSymbolAddress((void**)&seq, g_seq);

    // 1) seq = X @ W^T
    sgemm_kernel<<<(n_nodes + BM - 1) / BM, 256>>>(x, weight, seq, n_nodes);

    // 2) CSR build
    zero_counts_kernel<<<(n_nodes + 255) / 256, 256>>>(n_nodes);
    hist_kernel<<<(n_edges + 255) / 256, 256>>>(edge_row, n_edges);
    scan_kernel<<<1, 1024>>>(n_nodes);
    bucket_kernel<<<(n_edges + 255) / 256, 256>>>(edge_val, edge_row, edge_col, n_edges);

    // 3) gather + bias + PReLU (writes every out element exactly once)
    {
        int warps_per_block = 256 / 32;
        int grid = (n_nodes + warps_per_block - 1) / warps_per_block;
        gather_kernel<<<grid, 256>>>(seq, bias, alpha, out, n_nodes);
    }
}

// round 5
// speedup vs baseline: 2.3075x; 1.9131x over previous
#include <cuda_runtime.h>
#include <cuda_bf16.h>
#include <cstdint>

// GraphConvolution: out = PReLU( A_coo @ (X @ W^T) + bias )
//   x[40000,512] f32, weight[128,512] f32, bias[128], alpha[1],
//   edge_val[640000] f32, edge_row/col[640000] i32 -> out[40000,128] f32

#define D_IN   512
#define D_OUT  128
#define MAX_NODES 40000
#define MAX_EDGES 640000
#define SCAN_BLOCKS ((MAX_NODES + 1023) / 1024)

// Scratch (device globals: allocation-free rule)
__device__ float g_seq[(size_t)MAX_NODES * D_OUT];
__device__ int   g_counts[MAX_NODES];
__device__ int   g_row_start[MAX_NODES + 1];
__device__ int   g_cursor[MAX_NODES];
__device__ int   g_sorted_col[MAX_EDGES];
__device__ float g_sorted_val[MAX_EDGES];
__device__ int   g_bsum[SCAN_BLOCKS];
__device__ int   g_boff[SCAN_BLOCKS];

// ===========================================================================
// Base-ISA tensor-core helpers (sm_80+ PTX: compiles at sm_103 base target)
// ===========================================================================
__device__ __forceinline__ uint32_t smem_to_u32(const void* p) {
    uint32_t a;
    asm("{ .reg .u64 t; cvta.to.shared.u64 t, %1; cvt.u32.u64 %0, t; }"
        : "=r"(a) : "l"(p));
    return a;
}

#define LDSM_X4(r, addr) \
    asm volatile("ldmatrix.sync.aligned.m8n8.x4.shared.b16 {%0,%1,%2,%3}, [%4];" \
        : "=r"((r)[0]), "=r"((r)[1]), "=r"((r)[2]), "=r"((r)[3]) : "r"(addr))

#define MMA_BF16(d, a, b0, b1) \
    asm volatile("mma.sync.aligned.m16n8k16.row.col.f32.bf16.bf16.f32 " \
        "{%0,%1,%2,%3}, {%4,%5,%6,%7}, {%8,%9}, {%0,%1,%2,%3};" \
        : "+f"((d)[0]), "+f"((d)[1]), "+f"((d)[2]), "+f"((d)[3]) \
        : "r"((a)[0]), "r"((a)[1]), "r"((a)[2]), "r"((a)[3]), "r"(b0), "r"(b1))

#define STS128(addr, r0, r1, r2, r3) \
    asm volatile("st.shared.v4.b32 [%0], {%1, %2, %3, %4};" \
        :: "r"(addr), "r"(r0), "r"(r1), "r"(r2), "r"(r3) : "memory")

// 128-byte-row swizzle: bits[6:4] ^= bits[9:7] (keeps 16B alignment)
#define SW128(off) ((off) ^ (((off) >> 3) & 0x70))

__device__ __forceinline__ uint32_t pack_bf16x2(__nv_bfloat16 a, __nv_bfloat16 b) {
    __nv_bfloat162 t(a, b);
    return *reinterpret_cast<uint32_t*>(&t);
}

// Split 8 consecutive f32 into packed bf16 hi/lo pairs
__device__ __forceinline__ void split8(const float* f, uint32_t* hi, uint32_t* lo) {
#pragma unroll
    for (int q = 0; q < 4; q++) {
        float a = f[2*q], b = f[2*q+1];
        __nv_bfloat16 ha = __float2bfloat16(a);
        __nv_bfloat16 hb = __float2bfloat16(b);
        float fa = __bfloat162float(ha);
        float fb = __bfloat162float(hb);
        __nv_bfloat16 la = __float2bfloat16(a - fa);
        __nv_bfloat16 lb = __float2bfloat16(b - fb);
        hi[q] = pack_bf16x2(ha, hb);
        lo[q] = pack_bf16x2(la, lb);
    }
}

// smem layout (bytes): 4 tiles of [128 rows][64 bf16 cols] = 16 KB each
#define SM_AHI 0
#define SM_ALO 16384
#define SM_BHI 32768
#define SM_BLO 49152
#define SM_TOTAL 65536

// ===========================================================================
// GEMM: seq[M,128] = X[M,512] @ W^T via bf16 split-2 HMMA (mma.sync)
// Block tile 128x128; 8 warps (warp tile 64x32); K-chunks of 64.
// ===========================================================================
__global__ __launch_bounds__(256) void gemm_mma_kernel(
    const float* __restrict__ X, const float* __restrict__ W,
    float* __restrict__ seq, int M)
{
    extern __shared__ char smem[];
    const uint32_t sb = smem_to_u32(smem);
    const int tid  = threadIdx.x;
    const int lane = tid & 31;
    const int wid  = tid >> 5;
    const int block_m = blockIdx.x * 128;

    // loader mapping: two threads per row (cols 0-31 / 32-63)
    const int lrow = tid & 127;
    const int lcol = (tid >> 7) * 32;
    const int a_row = block_m + lrow;
    const bool a_ok = (a_row < M);

    // warp tile: 2 warps along M (64 each), 4 along N (32 each)
    const int wm = (wid & 1) * 64;
    const int wn = (wid >> 1) * 32;

    float acc[4][4][4];
#pragma unroll
    for (int i = 0; i < 4; i++)
#pragma unroll
        for (int j = 0; j < 4; j++)
#pragma unroll
            for (int q = 0; q < 4; q++) acc[i][j][q] = 0.f;

    for (int ch = 0; ch < 8; ch++) {
        const int k0 = ch * 64;
        __syncthreads();   // previous chunk's ldmatrix reads done before overwrite

        // ---- load f32 chunk, split to bf16 hi/lo, stage in swizzled smem ----
#pragma unroll
        for (int j = 0; j < 4; j++) {
            const int col = lcol + j * 8;
            const uint32_t off = SW128((uint32_t)(lrow * 128 + col * 2));

            float fa[8] = {0.f,0.f,0.f,0.f,0.f,0.f,0.f,0.f};
            if (a_ok) {
                const float* p = X + (size_t)a_row * D_IN + k0 + col;
                float4 v0 = *reinterpret_cast<const float4*>(p);
                float4 v1 = *reinterpret_cast<const float4*>(p + 4);
                fa[0]=v0.x; fa[1]=v0.y; fa[2]=v0.z; fa[3]=v0.w;
                fa[4]=v1.x; fa[5]=v1.y; fa[6]=v1.z; fa[7]=v1.w;
            }
            uint32_t hi[4], lo[4];
            split8(fa, hi, lo);
            STS128(sb + SM_AHI + off, hi[0], hi[1], hi[2], hi[3]);
            STS128(sb + SM_ALO + off, lo[0], lo[1], lo[2], lo[3]);

            const float* pw = W + (size_t)lrow * D_IN + k0 + col;
            float4 w0 = *reinterpret_cast<const float4*>(pw);
            float4 w1 = *reinterpret_cast<const float4*>(pw + 4);
            float fb[8] = {w0.x,w0.y,w0.z,w0.w,w1.x,w1.y,w1.z,w1.w};
            split8(fb, hi, lo);
            STS128(sb + SM_BHI + off, hi[0], hi[1], hi[2], hi[3]);
            STS128(sb + SM_BLO + off, lo[0], lo[1], lo[2], lo[3]);
        }
        __syncthreads();

        // ---- compute: 4 k-steps of 16 ----
#pragma unroll
        for (int k16 = 0; k16 < 4; k16++) {
            // B fragments: 4 n-atoms (x4 ldmatrix covers 2 atoms)
            uint32_t bh[8], bl[8];
#pragma unroll
            for (int h = 0; h < 2; h++) {
                const int row_b = wn + h * 16 + ((lane >> 4) & 1) * 8 + (lane & 7);
                const int kcol  = k16 * 16 + ((lane >> 3) & 1) * 8;
                const uint32_t off = SW128((uint32_t)(row_b * 128 + kcol * 2));
                LDSM_X4(&bh[h * 4], sb + SM_BHI + off);
                LDSM_X4(&bl[h * 4], sb + SM_BLO + off);
            }
            // A fragments per m-atom, 3 products each
#pragma unroll
            for (int am = 0; am < 4; am++) {
                const int row_a = wm + am * 16 + ((lane >> 3) & 1) * 8 + (lane & 7);
                const int kcol  = k16 * 16 + ((lane >> 4) & 1) * 8;
                const uint32_t off = SW128((uint32_t)(row_a * 128 + kcol * 2));
                uint32_t ah[4], al[4];
                LDSM_X4(ah, sb + SM_AHI + off);
                LDSM_X4(al, sb + SM_ALO + off);
#pragma unroll
                for (int an = 0; an < 4; an++) {
                    MMA_BF16(acc[am][an], ah, bh[an*2], bh[an*2+1]);
                    MMA_BF16(acc[am][an], ah, bl[an*2], bl[an*2+1]);
                    MMA_BF16(acc[am][an], al, bh[an*2], bh[an*2+1]);
                }
            }
        }
    }

    // ---- epilogue: fragment -> seq ----
    const int g = lane >> 2;
    const int t = lane & 3;
#pragma unroll
    for (int am = 0; am < 4; am++) {
#pragma unroll
        for (int an = 0; an < 4; an++) {
            const int c  = wn + an * 8 + t * 2;
            const int r0 = block_m + wm + am * 16 + g;
            const int r1 = r0 + 8;
            if (r0 < M) {
                float2 v = make_float2(acc[am][an][0], acc[am][an][1]);
                *reinterpret_cast<float2*>(seq + (size_t)r0 * D_OUT + c) = v;
            }
            if (r1 < M) {
                float2 v = make_float2(acc[am][an][2], acc[am][an][3]);
                *reinterpret_cast<float2*>(seq + (size_t)r1 * D_OUT + c) = v;
            }
        }
    }
}

// ===========================================================================
// CSR build: histogram -> 3-pass parallel scan -> bucket scatter
// ===========================================================================
__global__ void zero_counts_kernel(int n)
{
    int i = blockIdx.x * blockDim.x + threadIdx.x;
    if (i < n) g_counts[i] = 0;
}

__global__ void hist_kernel(const int* __restrict__ edge_row, int E)
{
    int i = blockIdx.x * blockDim.x + threadIdx.x;
    if (i < E) atomicAdd(&g_counts[edge_row[i]], 1);
}

__global__ __launch_bounds__(1024) void block_sum_kernel(int n)
{
    int gid = blockIdx.x * 1024 + threadIdx.x;
    int c = (gid < n) ? g_counts[gid] : 0;
    const int lane = threadIdx.x & 31, w = threadIdx.x >> 5;
#pragma unroll
    for (int o = 16; o > 0; o >>= 1) c += __shfl_down_sync(0xFFFFFFFFu, c, o);
    __shared__ int ws[32];
    if (lane == 0) ws[w] = c;
    __syncthreads();
    if (w == 0) {
        int v = ws[lane];
#pragma unroll
        for (int o = 16; o > 0; o >>= 1) v += __shfl_down_sync(0xFFFFFFFFu, v, o);
        if (lane == 0) g_bsum[blockIdx.x] = v;
    }
}

__global__ void bsum_scan_kernel(int nb, int n)
{
    const int tid = threadIdx.x;                 // 64 threads
    int v = (tid < nb) ? g_bsum[tid] : 0;
    const int lane = tid & 31, w = tid >> 5;
    int x = v;
#pragma unroll
    for (int o = 1; o < 32; o <<= 1) {
        int y = __shfl_up_sync(0xFFFFFFFFu, x, o);
        if (lane >= o) x += y;
    }
    __shared__ int ws[2];
    if (lane == 31) ws[w] = x;
    __syncthreads();
    if (w == 1) x += ws[0];
    if (tid < nb) g_boff[tid] = x - v;
    if (tid == nb - 1) g_row_start[n] = x;
}

__global__ __launch_bounds__(1024) void scan_pass3_kernel(int n)
{
    int gid = blockIdx.x * 1024 + threadIdx.x;
    int c = (gid < n) ? g_counts[gid] : 0;
    const int lane = threadIdx.x & 31, w = threadIdx.x >> 5;
    int x = c;
#pragma unroll
    for (int o = 1; o < 32; o <<= 1) {
        int y = __shfl_up_sync(0xFFFFFFFFu, x, o);
        if (lane >= o) x += y;
    }
    __shared__ int ws[32];
    if (lane == 31) ws[w] = x;
    __syncthreads();
    if (w == 0) {
        int y = ws[lane];
#pragma unroll
        for (int o = 1; o < 32; o <<= 1) {
            int z = __shfl_up_sync(0xFFFFFFFFu, y, o);
            if (lane >= o) y += z;
        }
        ws[lane] = y;
    }
    __syncthreads();
    int excl = x - c + (w ? ws[w - 1] : 0) + g_boff[blockIdx.x];
    if (gid < n) { g_row_start[gid] = excl; g_cursor[gid] = excl; }
}

__global__ void bucket_kernel(const float* __restrict__ edge_val,
                              const int*   __restrict__ edge_row,
                              const int*   __restrict__ edge_col, int E)
{
    int i = blockIdx.x * blockDim.x + threadIdx.x;
    if (i >= E) return;
    int r = edge_row[i];
    int pos = atomicAdd(&g_cursor[r], 1);
    g_sorted_col[pos] = edge_col[i];
    g_sorted_val[pos] = edge_val[i];
}

// ===========================================================================
// Gather: one warp per row; fused bias + PReLU; 2-way ILP
// ===========================================================================
__global__ __launch_bounds__(256) void gather_kernel(
    const float* __restrict__ seq,
    const float* __restrict__ bias,
    const float* __restrict__ alpha,
    float* __restrict__ out, int n_nodes)
{
    int w = blockIdx.x * (blockDim.x >> 5) + (threadIdx.x >> 5);
    if (w >= n_nodes) return;
    const int lane = threadIdx.x & 31;

    const int s = g_row_start[w];
    const int e = g_row_start[w + 1];

    float4 acc = make_float4(0.f, 0.f, 0.f, 0.f);
    int i = s;
    for (; i + 1 < e; i += 2) {
        int   c0 = g_sorted_col[i],     c1 = g_sorted_col[i + 1];
        float v0 = g_sorted_val[i],     v1 = g_sorted_val[i + 1];
        float4 s0 = *reinterpret_cast<const float4*>(seq + (size_t)c0 * D_OUT + lane * 4);
        float4 s1 = *reinterpret_cast<const float4*>(seq + (size_t)c1 * D_OUT + lane * 4);
        acc.x = fmaf(v0, s0.x, acc.x); acc.y = fmaf(v0, s0.y, acc.y);
        acc.z = fmaf(v0, s0.z, acc.z); acc.w = fmaf(v0, s0.w, acc.w);
        acc.x = fmaf(v1, s1.x, acc.x); acc.y = fmaf(v1, s1.y, acc.y);
        acc.z = fmaf(v1, s1.z, acc.z); acc.w = fmaf(v1, s1.w, acc.w);
    }
    if (i < e) {
        int   c = g_sorted_col[i];
        float v = g_sorted_val[i];
        float4 sv = *reinterpret_cast<const float4*>(seq + (size_t)c * D_OUT + lane * 4);
        acc.x = fmaf(v, sv.x, acc.x); acc.y = fmaf(v, sv.y, acc.y);
        acc.z = fmaf(v, sv.z, acc.z); acc.w = fmaf(v, sv.w, acc.w);
    }

    const float a = alpha[0];
    float4 b = *reinterpret_cast<const float4*>(bias + lane * 4);
    acc.x += b.x; acc.y += b.y; acc.z += b.z; acc.w += b.w;
    acc.x = acc.x > 0.f ? acc.x : a * acc.x;
    acc.y = acc.y > 0.f ? acc.y : a * acc.y;
    acc.z = acc.z > 0.f ? acc.z : a * acc.z;
    acc.w = acc.w > 0.f ? acc.w : a * acc.w;

    *reinterpret_cast<float4*>(out + (size_t)w * D_OUT + lane * 4) = acc;
}

// ===========================================================================
extern "C" void kernel_launch(void* const* d_in, const int* in_sizes, int n_in,
                              void* d_out, int out_size)
{
    const float* x        = (const float*)d_in[0];
    const float* weight   = (const float*)d_in[1];
    const float* bias     = (const float*)d_in[2];
    const float* alpha    = (const float*)d_in[3];
    const float* edge_val = (const float*)d_in[4];
    const int*   edge_row = (const int*)d_in[5];
    const int*   edge_col = (const int*)d_in[6];
    float*       out      = (float*)d_out;

    const int n_nodes = in_sizes[0] / D_IN;     // 40000
    const int n_edges = in_sizes[4];            // 640000

    float* seq = nullptr;
    cudaGetSymbolAddress((void**)&seq, g_seq);

    // 1) seq = X @ W^T  (bf16 split-2 HMMA)
    {
        static bool attr_set = false;
        if (!attr_set) {
            cudaFuncSetAttribute(gemm_mma_kernel,
                                 cudaFuncAttributeMaxDynamicSharedMemorySize, SM_TOTAL);
            attr_set = true;
        }
        int grid = (n_nodes + 127) / 128;       // 313
        gemm_mma_kernel<<<grid, 256, SM_TOTAL>>>(x, weight, seq, n_nodes);
    }

    // 2) CSR build
    zero_counts_kernel<<<(n_nodes + 255) / 256, 256>>>(n_nodes);
    hist_kernel<<<(n_edges + 255) / 256, 256>>>(edge_row, n_edges);
    {
        int nb = (n_nodes + 1023) / 1024;       // 40
        block_sum_kernel<<<nb, 1024>>>(n_nodes);
        bsum_scan_kernel<<<1, 64>>>(nb, n_nodes);
        scan_pass3_kernel<<<nb, 1024>>>(n_nodes);
    }
    bucket_kernel<<<(n_edges + 255) / 256, 256>>>(edge_val, edge_row, edge_col, n_edges);

    // 3) gather + bias + PReLU
    {
        int warps_per_block = 256 / 32;
        int grid = (n_nodes + warps_per_block - 1) / warps_per_block;
        gather_kernel<<<grid, 256>>>(seq, bias, alpha, out, n_nodes);
    }
}

// round 6
// speedup vs baseline: 3.0738x; 1.3321x over previous
#include <cuda_runtime.h>
#include <cuda_bf16.h>
#include <cstdint>

// GraphConvolution: out = PReLU( A_coo @ (X @ W^T) + bias )
//   x[40000,512] f32, weight[128,512] f32, bias[128], alpha[1],
//   edge_val[640000] f32, edge_row/col[640000] i32 -> out[40000,128] f32

#define D_IN   512
#define D_OUT  128
#define MAX_NODES 40000
#define MAX_EDGES 640000
#define SCAN_BLOCKS ((MAX_NODES + 1023) / 1024)

// Scratch (device globals: allocation-free rule)
__device__ float g_seq[(size_t)MAX_NODES * D_OUT];
__device__ int   g_counts[MAX_NODES];
__device__ int   g_row_start[MAX_NODES + 1];
__device__ int   g_cursor[MAX_NODES];
__device__ int2  g_sorted[MAX_EDGES];          // (col, val-bits) packed
__device__ int   g_bsum[SCAN_BLOCKS];
__device__ int   g_boff[SCAN_BLOCKS];
__device__ __nv_bfloat16 g_whi[D_OUT * D_IN];  // pre-split weight hi
__device__ __nv_bfloat16 g_wlo[D_OUT * D_IN];  // pre-split weight lo

// ===========================================================================
// Helpers (base-ISA PTX only; must compile at .target sm_103)
// ===========================================================================
__device__ __forceinline__ uint32_t smem_to_u32(const void* p) {
    uint32_t a;
    asm("{ .reg .u64 t; cvta.to.shared.u64 t, %1; cvt.u32.u64 %0, t; }"
        : "=r"(a) : "l"(p));
    return a;
}

#define LDSM_X4(r, addr) \
    asm volatile("ldmatrix.sync.aligned.m8n8.x4.shared.b16 {%0,%1,%2,%3}, [%4];" \
        : "=r"((r)[0]), "=r"((r)[1]), "=r"((r)[2]), "=r"((r)[3]) : "r"(addr))

#define MMA_BF16(d, a, b0, b1) \
    asm volatile("mma.sync.aligned.m16n8k16.row.col.f32.bf16.bf16.f32 " \
        "{%0,%1,%2,%3}, {%4,%5,%6,%7}, {%8,%9}, {%0,%1,%2,%3};" \
        : "+f"((d)[0]), "+f"((d)[1]), "+f"((d)[2]), "+f"((d)[3]) \
        : "r"((a)[0]), "r"((a)[1]), "r"((a)[2]), "r"((a)[3]), "r"(b0), "r"(b1))

#define STS128(addr, r0, r1, r2, r3) \
    asm volatile("st.shared.v4.b32 [%0], {%1, %2, %3, %4};" \
        :: "r"(addr), "r"(r0), "r"(r1), "r"(r2), "r"(r3) : "memory")

#define CP_ASYNC16(dst, src) \
    asm volatile("cp.async.cg.shared.global [%0], [%1], 16;" \
        :: "r"(dst), "l"(src) : "memory")
#define CP_COMMIT() asm volatile("cp.async.commit_group;" ::: "memory")
#define CP_WAIT0()  asm volatile("cp.async.wait_group 0;" ::: "memory")

// 128-byte-row swizzle: bits[6:4] ^= bits[9:7]
#define SW128(off) ((off) ^ (((off) >> 3) & 0x70))

__device__ __forceinline__ uint32_t pack_bf16x2(__nv_bfloat16 a, __nv_bfloat16 b) {
    __nv_bfloat162 t(a, b);
    return *reinterpret_cast<uint32_t*>(&t);
}

__device__ __forceinline__ void split8(const float* f, uint32_t* hi, uint32_t* lo) {
#pragma unroll
    for (int q = 0; q < 4; q++) {
        float a = f[2*q], b = f[2*q+1];
        __nv_bfloat16 ha = __float2bfloat16(a);
        __nv_bfloat16 hb = __float2bfloat16(b);
        __nv_bfloat16 la = __float2bfloat16(a - __bfloat162float(ha));
        __nv_bfloat16 lb = __float2bfloat16(b - __bfloat162float(hb));
        hi[q] = pack_bf16x2(ha, hb);
        lo[q] = pack_bf16x2(la, lb);
    }
}

// ===========================================================================
// W prep: split weight into bf16 hi/lo once
// ===========================================================================
__global__ void prep_w_kernel(const float* __restrict__ W)
{
    int i = blockIdx.x * blockDim.x + threadIdx.x;   // 65536 elements
    if (i < D_OUT * D_IN) {
        float w = W[i];
        __nv_bfloat16 h = __float2bfloat16(w);
        g_whi[i] = h;
        g_wlo[i] = __float2bfloat16(w - __bfloat162float(h));
    }
}

// smem layout (bytes)
#define SM_AHI 0
#define SM_ALO 16384
#define SM_B   32768                   // [stage][hi/lo] 16KB each
#define SM_TOTAL (32768 + 2 * 32768)   // 98304

// ===========================================================================
// GEMM: seq[M,128] = X[M,512] @ W^T via bf16 split-2 HMMA
// Block tile 128x128; 8 warps (64x32 each); K-chunks of 64; B via cp.async.
// ===========================================================================
__global__ __launch_bounds__(256) void gemm_mma_kernel(
    const float* __restrict__ X, float* __restrict__ seq, int M)
{
    extern __shared__ char smem[];
    const uint32_t sb = smem_to_u32(smem);
    const int tid  = threadIdx.x;
    const int lane = tid & 31;
    const int wid  = tid >> 5;
    const int block_m = blockIdx.x * 128;

    const int lrow = tid & 127;
    const int lcol = (tid >> 7) * 32;
    const int a_row = block_m + lrow;
    const bool a_ok = (a_row < M);

    const int wm = (wid & 1) * 64;
    const int wn = (wid >> 1) * 32;

    float acc[4][4][4];
#pragma unroll
    for (int i = 0; i < 4; i++)
#pragma unroll
        for (int j = 0; j < 4; j++)
#pragma unroll
            for (int q = 0; q < 4; q++) acc[i][j][q] = 0.f;

    // B stage loader: 128 rows x 128B, 8x16B per row, 4 iters of 256 threads
    auto load_b = [&](int ch, int st) {
        const int k0 = ch * 64;
        const uint32_t bhi = sb + SM_B + st * 32768;
        const uint32_t blo = bhi + 16384;
#pragma unroll
        for (int it = 0; it < 4; it++) {
            int idx = it * 256 + tid;
            int row = idx >> 3;
            int seg = idx & 7;
            uint32_t off = SW128((uint32_t)(row * 128 + seg * 16));
            const __nv_bfloat16* sh = g_whi + (size_t)row * D_IN + k0 + seg * 8;
            const __nv_bfloat16* sl = g_wlo + (size_t)row * D_IN + k0 + seg * 8;
            CP_ASYNC16(bhi + off, sh);
            CP_ASYNC16(blo + off, sl);
        }
        CP_COMMIT();
    };

    load_b(0, 0);

    for (int ch = 0; ch < 8; ch++) {
        const int st = ch & 1;
        const int k0 = ch * 64;

        // ---- A: load f32, split, stage (single-buffered smem) ----
#pragma unroll
        for (int j = 0; j < 4; j++) {
            const int col = lcol + j * 8;
            const uint32_t off = SW128((uint32_t)(lrow * 128 + col * 2));
            float fa[8] = {0.f,0.f,0.f,0.f,0.f,0.f,0.f,0.f};
            if (a_ok) {
                const float* p = X + (size_t)a_row * D_IN + k0 + col;
                float4 v0 = *reinterpret_cast<const float4*>(p);
                float4 v1 = *reinterpret_cast<const float4*>(p + 4);
                fa[0]=v0.x; fa[1]=v0.y; fa[2]=v0.z; fa[3]=v0.w;
                fa[4]=v1.x; fa[5]=v1.y; fa[6]=v1.z; fa[7]=v1.w;
            }
            uint32_t hi[4], lo[4];
            split8(fa, hi, lo);
            STS128(sb + SM_AHI + off, hi[0], hi[1], hi[2], hi[3]);
            STS128(sb + SM_ALO + off, lo[0], lo[1], lo[2], lo[3]);
        }

        CP_WAIT0();          // B(ch) resident
        __syncthreads();     // A stores + B visible

        if (ch < 7) load_b(ch + 1, st ^ 1);   // overlaps MMA below

        const uint32_t bhi_base = sb + SM_B + st * 32768;
        const uint32_t blo_base = bhi_base + 16384;

#pragma unroll
        for (int k16 = 0; k16 < 4; k16++) {
            uint32_t bh[8], bl[8];
#pragma unroll
            for (int h = 0; h < 2; h++) {
                const int row_b = wn + h * 16 + ((lane >> 4) & 1) * 8 + (lane & 7);
                const int kcol  = k16 * 16 + ((lane >> 3) & 1) * 8;
                const uint32_t off = SW128((uint32_t)(row_b * 128 + kcol * 2));
                LDSM_X4(&bh[h * 4], bhi_base + off);
                LDSM_X4(&bl[h * 4], blo_base + off);
            }
#pragma unroll
            for (int am = 0; am < 4; am++) {
                const int row_a = wm + am * 16 + ((lane >> 3) & 1) * 8 + (lane & 7);
                const int kcol  = k16 * 16 + ((lane >> 4) & 1) * 8;
                const uint32_t off = SW128((uint32_t)(row_a * 128 + kcol * 2));
                uint32_t ah[4], al[4];
                LDSM_X4(ah, sb + SM_AHI + off);
                LDSM_X4(al, sb + SM_ALO + off);
#pragma unroll
                for (int an = 0; an < 4; an++) {
                    MMA_BF16(acc[am][an], ah, bh[an*2], bh[an*2+1]);
                    MMA_BF16(acc[am][an], ah, bl[an*2], bl[an*2+1]);
                    MMA_BF16(acc[am][an], al, bh[an*2], bh[an*2+1]);
                }
            }
        }
        __syncthreads();     // readers done before next A overwrite
    }

    // ---- epilogue ----
    const int g = lane >> 2;
    const int t = lane & 3;
#pragma unroll
    for (int am = 0; am < 4; am++) {
#pragma unroll
        for (int an = 0; an < 4; an++) {
            const int c  = wn + an * 8 + t * 2;
            const int r0 = block_m + wm + am * 16 + g;
            const int r1 = r0 + 8;
            if (r0 < M) {
                float2 v = make_float2(acc[am][an][0], acc[am][an][1]);
                *reinterpret_cast<float2*>(seq + (size_t)r0 * D_OUT + c) = v;
            }
            if (r1 < M) {
                float2 v = make_float2(acc[am][an][2], acc[am][an][3]);
                *reinterpret_cast<float2*>(seq + (size_t)r1 * D_OUT + c) = v;
            }
        }
    }
}

// ===========================================================================
// CSR build
// ===========================================================================
__global__ void zero_counts_kernel(int n)
{
    int i = blockIdx.x * blockDim.x + threadIdx.x;
    if (i < n) g_counts[i] = 0;
}

__global__ void hist_kernel(const int* __restrict__ edge_row, int E)
{
    int i = blockIdx.x * blockDim.x + threadIdx.x;
    if (i < E) atomicAdd(&g_counts[edge_row[i]], 1);
}

__global__ __launch_bounds__(1024) void block_sum_kernel(int n)
{
    int gid = blockIdx.x * 1024 + threadIdx.x;
    int c = (gid < n) ? g_counts[gid] : 0;
    const int lane = threadIdx.x & 31, w = threadIdx.x >> 5;
#pragma unroll
    for (int o = 16; o > 0; o >>= 1) c += __shfl_down_sync(0xFFFFFFFFu, c, o);
    __shared__ int ws[32];
    if (lane == 0) ws[w] = c;
    __syncthreads();
    if (w == 0) {
        int v = ws[lane];
#pragma unroll
        for (int o = 16; o > 0; o >>= 1) v += __shfl_down_sync(0xFFFFFFFFu, v, o);
        if (lane == 0) g_bsum[blockIdx.x] = v;
    }
}

__global__ void bsum_scan_kernel(int nb, int n)
{
    const int tid = threadIdx.x;                 // 64 threads
    int v = (tid < nb) ? g_bsum[tid] : 0;
    const int lane = tid & 31, w = tid >> 5;
    int x = v;
#pragma unroll
    for (int o = 1; o < 32; o <<= 1) {
        int y = __shfl_up_sync(0xFFFFFFFFu, x, o);
        if (lane >= o) x += y;
    }
    __shared__ int ws[2];
    if (lane == 31) ws[w] = x;
    __syncthreads();
    if (w == 1) x += ws[0];
    if (tid < nb) g_boff[tid] = x - v;
    if (tid == nb - 1) g_row_start[n] = x;
}

__global__ __launch_bounds__(1024) void scan_pass3_kernel(int n)
{
    int gid = blockIdx.x * 1024 + threadIdx.x;
    int c = (gid < n) ? g_counts[gid] : 0;
    const int lane = threadIdx.x & 31, w = threadIdx.x >> 5;
    int x = c;
#pragma unroll
    for (int o = 1; o < 32; o <<= 1) {
        int y = __shfl_up_sync(0xFFFFFFFFu, x, o);
        if (lane >= o) x += y;
    }
    __shared__ int ws[32];
    if (lane == 31) ws[w] = x;
    __syncthreads();
    if (w == 0) {
        int y = ws[lane];
#pragma unroll
        for (int o = 1; o < 32; o <<= 1) {
            int z = __shfl_up_sync(0xFFFFFFFFu, y, o);
            if (lane >= o) y += z;
        }
        ws[lane] = y;
    }
    __syncthreads();
    int excl = x - c + (w ? ws[w - 1] : 0) + g_boff[blockIdx.x];
    if (gid < n) { g_row_start[gid] = excl; g_cursor[gid] = excl; }
}

__global__ void bucket_kernel(const float* __restrict__ edge_val,
                              const int*   __restrict__ edge_row,
                              const int*   __restrict__ edge_col, int E)
{
    int i = blockIdx.x * blockDim.x + threadIdx.x;
    if (i >= E) return;
    int r = edge_row[i];
    int pos = atomicAdd(&g_cursor[r], 1);
    g_sorted[pos] = make_int2(edge_col[i], __float_as_int(edge_val[i]));
}

// ===========================================================================
// Gather: one warp per row; fused bias + PReLU; 4-way ILP; packed edges
// ===========================================================================
__global__ __launch_bounds__(256) void gather_kernel(
    const float* __restrict__ seq,
    const float* __restrict__ bias,
    const float* __restrict__ alpha,
    float* __restrict__ out, int n_nodes)
{
    int w = blockIdx.x * (blockDim.x >> 5) + (threadIdx.x >> 5);
    if (w >= n_nodes) return;
    const int lane = threadIdx.x & 31;

    const int s = g_row_start[w];
    const int e = g_row_start[w + 1];

    float4 acc = make_float4(0.f, 0.f, 0.f, 0.f);
    int i = s;
    for (; i + 3 < e; i += 4) {
        int2 p0 = g_sorted[i],   p1 = g_sorted[i+1];
        int2 p2 = g_sorted[i+2], p3 = g_sorted[i+3];
        float4 s0 = *reinterpret_cast<const float4*>(seq + (size_t)p0.x * D_OUT + lane * 4);
        float4 s1 = *reinterpret_cast<const float4*>(seq + (size_t)p1.x * D_OUT + lane * 4);
        float4 s2 = *reinterpret_cast<const float4*>(seq + (size_t)p2.x * D_OUT + lane * 4);
        float4 s3 = *reinterpret_cast<const float4*>(seq + (size_t)p3.x * D_OUT + lane * 4);
        float v0 = __int_as_float(p0.y), v1 = __int_as_float(p1.y);
        float v2 = __int_as_float(p2.y), v3 = __int_as_float(p3.y);
        acc.x = fmaf(v0, s0.x, acc.x); acc.y = fmaf(v0, s0.y, acc.y);
        acc.z = fmaf(v0, s0.z, acc.z); acc.w = fmaf(v0, s0.w, acc.w);
        acc.x = fmaf(v1, s1.x, acc.x); acc.y = fmaf(v1, s1.y, acc.y);
        acc.z = fmaf(v1, s1.z, acc.z); acc.w = fmaf(v1, s1.w, acc.w);
        acc.x = fmaf(v2, s2.x, acc.x); acc.y = fmaf(v2, s2.y, acc.y);
        acc.z = fmaf(v2, s2.z, acc.z); acc.w = fmaf(v2, s2.w, acc.w);
        acc.x = fmaf(v3, s3.x, acc.x); acc.y = fmaf(v3, s3.y, acc.y);
        acc.z = fmaf(v3, s3.z, acc.z); acc.w = fmaf(v3, s3.w, acc.w);
    }
    for (; i < e; i++) {
        int2 p = g_sorted[i];
        float v = __int_as_float(p.y);
        float4 sv = *reinterpret_cast<const float4*>(seq + (size_t)p.x * D_OUT + lane * 4);
        acc.x = fmaf(v, sv.x, acc.x); acc.y = fmaf(v, sv.y, acc.y);
        acc.z = fmaf(v, sv.z, acc.z); acc.w = fmaf(v, sv.w, acc.w);
    }

    const float a = alpha[0];
    float4 b = *reinterpret_cast<const float4*>(bias + lane * 4);
    acc.x += b.x; acc.y += b.y; acc.z += b.z; acc.w += b.w;
    acc.x = acc.x > 0.f ? acc.x : a * acc.x;
    acc.y = acc.y > 0.f ? acc.y : a * acc.y;
    acc.z = acc.z > 0.f ? acc.z : a * acc.z;
    acc.w = acc.w > 0.f ? acc.w : a * acc.w;

    *reinterpret_cast<float4*>(out + (size_t)w * D_OUT + lane * 4) = acc;
}

// ===========================================================================
extern "C" void kernel_launch(void* const* d_in, const int* in_sizes, int n_in,
                              void* d_out, int out_size)
{
    const float* x        = (const float*)d_in[0];
    const float* weight   = (const float*)d_in[1];
    const float* bias     = (const float*)d_in[2];
    const float* alpha    = (const float*)d_in[3];
    const float* edge_val = (const float*)d_in[4];
    const int*   edge_row = (const int*)d_in[5];
    const int*   edge_col = (const int*)d_in[6];
    float*       out      = (float*)d_out;

    const int n_nodes = in_sizes[0] / D_IN;     // 40000
    const int n_edges = in_sizes[4];            // 640000

    float* seq = nullptr;
    cudaGetSymbolAddress((void**)&seq, g_seq);

    static cudaStream_t s2 = nullptr;
    static cudaEvent_t evA = nullptr, evB = nullptr;
    static bool init_done = false;
    if (!init_done) {
        cudaStreamCreateWithFlags(&s2, cudaStreamNonBlocking);
        cudaEventCreateWithFlags(&evA, cudaEventDisableTiming);
        cudaEventCreateWithFlags(&evB, cudaEventDisableTiming);
        cudaFuncSetAttribute(gemm_mma_kernel,
                             cudaFuncAttributeMaxDynamicSharedMemorySize, SM_TOTAL);
        init_done = true;
    }

    // fork: CSR build on s2 runs concurrently with GEMM on the main stream
    cudaEventRecord(evA, 0);
    cudaStreamWaitEvent(s2, evA, 0);

    // --- main stream: W prep + GEMM ---
    prep_w_kernel<<<(D_OUT * D_IN + 255) / 256, 256>>>(weight);
    gemm_mma_kernel<<<(n_nodes + 127) / 128, 256, SM_TOTAL>>>(x, seq, n_nodes);

    // --- s2: CSR build ---
    zero_counts_kernel<<<(n_nodes + 255) / 256, 256, 0, s2>>>(n_nodes);
    hist_kernel<<<(n_edges + 255) / 256, 256, 0, s2>>>(edge_row, n_edges);
    {
        int nb = (n_nodes + 1023) / 1024;
        block_sum_kernel<<<nb, 1024, 0, s2>>>(n_nodes);
        bsum_scan_kernel<<<1, 64, 0, s2>>>(nb, n_nodes);
        scan_pass3_kernel<<<nb, 1024, 0, s2>>>(n_nodes);
    }
    bucket_kernel<<<(n_edges + 255) / 256, 256, 0, s2>>>(edge_val, edge_row, edge_col, n_edges);
    cudaEventRecord(evB, s2);

    // join, then gather
    cudaStreamWaitEvent(0, evB, 0);
    {
        int warps_per_block = 256 / 32;
        int grid = (n_nodes + warps_per_block - 1) / warps_per_block;
        gather_kernel<<<grid, 256>>>(seq, bias, alpha, out, n_nodes);
    }
}

// round 8
// speedup vs baseline: 3.8752x; 1.2607x over previous
#include <cuda_runtime.h>
#include <cuda_bf16.h>
#include <cstdint>

// GraphConvolution: out = PReLU( A_coo @ (X @ W^T) + bias )
//   x[40000,512] f32, weight[128,512] f32, bias[128], alpha[1],
//   edge_val[640000] f32, edge_row/col[640000] i32 -> out[40000,128] f32

#define D_IN   512
#define D_OUT  128
#define MAX_NODES 40000
#define MAX_EDGES 640000
#define SCAN_BLOCKS ((MAX_NODES + 1023) / 1024)

// Scratch (device globals: allocation-free rule)
__device__ float g_seq[(size_t)MAX_NODES * D_OUT];
__device__ int   g_counts[MAX_NODES];
__device__ int   g_row_start[MAX_NODES + 1];
__device__ int   g_cursor[MAX_NODES];
__device__ int2  g_sorted[MAX_EDGES];          // (col, val-bits) packed
__device__ int   g_bsum[SCAN_BLOCKS];
__device__ int   g_boff[SCAN_BLOCKS];
__device__ __nv_bfloat16 g_whi[D_OUT * D_IN];  // pre-split weight hi
__device__ __nv_bfloat16 g_wlo[D_OUT * D_IN];  // pre-split weight lo

// ===========================================================================
// Helpers (base-ISA PTX only; must compile at .target sm_103)
// ===========================================================================
__device__ __forceinline__ uint32_t smem_to_u32(const void* p) {
    uint32_t a;
    asm("{ .reg .u64 t; cvta.to.shared.u64 t, %1; cvt.u32.u64 %0, t; }"
        : "=r"(a) : "l"(p));
    return a;
}

#define LDSM_X4(r, addr) \
    asm volatile("ldmatrix.sync.aligned.m8n8.x4.shared.b16 {%0,%1,%2,%3}, [%4];" \
        : "=r"((r)[0]), "=r"((r)[1]), "=r"((r)[2]), "=r"((r)[3]) : "r"(addr))

#define MMA_BF16(d, a, b0, b1) \
    asm volatile("mma.sync.aligned.m16n8k16.row.col.f32.bf16.bf16.f32 " \
        "{%0,%1,%2,%3}, {%4,%5,%6,%7}, {%8,%9}, {%0,%1,%2,%3};" \
        : "+f"((d)[0]), "+f"((d)[1]), "+f"((d)[2]), "+f"((d)[3]) \
        : "r"((a)[0]), "r"((a)[1]), "r"((a)[2]), "r"((a)[3]), "r"(b0), "r"(b1))

#define STS128(addr, r0, r1, r2, r3) \
    asm volatile("st.shared.v4.b32 [%0], {%1, %2, %3, %4};" \
        :: "r"(addr), "r"(r0), "r"(r1), "r"(r2), "r"(r3) : "memory")

#define CP_ASYNC16(dst, src) \
    asm volatile("cp.async.cg.shared.global [%0], [%1], 16;" \
        :: "r"(dst), "l"(src) : "memory")
#define CP_COMMIT() asm volatile("cp.async.commit_group;" ::: "memory")
#define CP_WAIT0()  asm volatile("cp.async.wait_group 0;" ::: "memory")

// 128-byte-row swizzle: bits[6:4] ^= bits[9:7]
#define SW128(off) ((off) ^ (((off) >> 3) & 0x70))

// Fast split: hi = truncate-to-bf16 (exact bit op), lo = a - hi (exact FADD),
// hi pair packed with one PRMT, lo pair with one cvt.rn.bf16x2.f32.
// Dropped term in the 3-product scheme is <= 2^-17 relative.
__device__ __forceinline__ void split8_fast(const float* f, uint32_t* hi, uint32_t* lo) {
#pragma unroll
    for (int q = 0; q < 4; q++) {
        float a = f[2*q], b = f[2*q+1];
        uint32_t ua = __float_as_uint(a), ub = __float_as_uint(b);
        hi[q] = __byte_perm(ua, ub, 0x7632);               // low16=a.hi, high16=b.hi
        float ha = __uint_as_float(ua & 0xFFFF0000u);
        float hb = __uint_as_float(ub & 0xFFFF0000u);
        __nv_bfloat162 l2 = __float22bfloat162_rn(make_float2(a - ha, b - hb));
        lo[q] = *reinterpret_cast<uint32_t*>(&l2);
    }
}

// ===========================================================================
// W prep: split weight into bf16 hi/lo once (RN split; tiny kernel)
// ===========================================================================
__global__ void prep_w_kernel(const float* __restrict__ W)
{
    int i = blockIdx.x * blockDim.x + threadIdx.x;
    if (i < D_OUT * D_IN) {
        float w = W[i];
        __nv_bfloat16 h = __float2bfloat16(w);
        g_whi[i] = h;
        g_wlo[i] = __float2bfloat16(w - __bfloat162float(h));
    }
}

// smem layout (bytes): A[stage][hi|lo] then B[stage][hi|lo], 16KB tiles
#define SM_A 0
#define SM_B 65536
#define SM_TOTAL 131072

// ===========================================================================
// GEMM: seq[M,128] = X[M,512] @ W^T via bf16 split-2 HMMA
// 128x128 block tile; 8 warps (64x32); K-chunks of 64; A+B double-buffered.
// ===========================================================================
__global__ __launch_bounds__(256) void gemm_mma_kernel(
    const float* __restrict__ X, float* __restrict__ seq, int M)
{
    extern __shared__ char smem[];
    const uint32_t sb = smem_to_u32(smem);
    const int tid  = threadIdx.x;
    const int lane = tid & 31;
    const int wid  = tid >> 5;
    const int block_m = blockIdx.x * 128;

    const int lrow = tid & 127;          // 2 threads per A row
    const int lcol = (tid >> 7) * 32;    // cols 0-31 / 32-63
    const int a_row = block_m + lrow;
    const bool a_ok = (a_row < M);

    const int wm = (wid & 1) * 64;
    const int wn = (wid >> 1) * 32;

    float acc[4][4][4];
#pragma unroll
    for (int i = 0; i < 4; i++)
#pragma unroll
        for (int j = 0; j < 4; j++)
#pragma unroll
            for (int q = 0; q < 4; q++) acc[i][j][q] = 0.f;

    float4 afa[8];   // prefetched A f32 chunk (32 floats)

    auto load_a = [&](int ch) {
        const int k0 = ch * 64;
#pragma unroll
        for (int j = 0; j < 4; j++) {
            if (a_ok) {
                const float* p = X + (size_t)a_row * D_IN + k0 + lcol + j * 8;
                afa[2*j]   = *reinterpret_cast<const float4*>(p);
                afa[2*j+1] = *reinterpret_cast<const float4*>(p + 4);
            } else {
                afa[2*j] = afa[2*j+1] = make_float4(0.f, 0.f, 0.f, 0.f);
            }
        }
    };

    auto store_a = [&](int st) {
        const uint32_t ahi = sb + SM_A + st * 32768;
        const uint32_t alo = ahi + 16384;
#pragma unroll
        for (int j = 0; j < 4; j++) {
            const int col = lcol + j * 8;
            const uint32_t off = SW128((uint32_t)(lrow * 128 + col * 2));
            float f[8] = {afa[2*j].x, afa[2*j].y, afa[2*j].z, afa[2*j].w,
                          afa[2*j+1].x, afa[2*j+1].y, afa[2*j+1].z, afa[2*j+1].w};
            uint32_t hi[4], lo[4];
            split8_fast(f, hi, lo);
            STS128(ahi + off, hi[0], hi[1], hi[2], hi[3]);
            STS128(alo + off, lo[0], lo[1], lo[2], lo[3]);
        }
    };

    auto load_b = [&](int ch, int st) {
        const int k0 = ch * 64;
        const uint32_t bhi = sb + SM_B + st * 32768;
        const uint32_t blo = bhi + 16384;
#pragma unroll
        for (int it = 0; it < 4; it++) {
            int idx = it * 256 + tid;
            int row = idx >> 3;
            int seg = idx & 7;
            uint32_t off = SW128((uint32_t)(row * 128 + seg * 16));
            CP_ASYNC16(bhi + off, g_whi + (size_t)row * D_IN + k0 + seg * 8);
            CP_ASYNC16(blo + off, g_wlo + (size_t)row * D_IN + k0 + seg * 8);
        }
        CP_COMMIT();
    };

    load_a(0);
    load_b(0, 0);

    for (int ch = 0; ch < 8; ch++) {
        const int st = ch & 1;

        store_a(st);                       // overlaps previous chunk's tensor work
        if (ch < 7) load_a(ch + 1);        // LDG prefetch into regs

        CP_WAIT0();                        // B(ch) resident
        __syncthreads();                   // A stores + B visible to all warps

        if (ch < 7) load_b(ch + 1, st ^ 1);   // cp.async overlaps MMA below

        const uint32_t ahi_base = sb + SM_A + st * 32768;
        const uint32_t alo_base = ahi_base + 16384;
        const uint32_t bhi_base = sb + SM_B + st * 32768;
        const uint32_t blo_base = bhi_base + 16384;

#pragma unroll
        for (int k16 = 0; k16 < 4; k16++) {
            uint32_t bh[8], bl[8];
#pragma unroll
            for (int h = 0; h < 2; h++) {
                const int row_b = wn + h * 16 + ((lane >> 4) & 1) * 8 + (lane & 7);
                const int kcol  = k16 * 16 + ((lane >> 3) & 1) * 8;
                const uint32_t off = SW128((uint32_t)(row_b * 128 + kcol * 2));
                LDSM_X4(&bh[h * 4], bhi_base + off);
                LDSM_X4(&bl[h * 4], blo_base + off);
            }
#pragma unroll
            for (int am = 0; am < 4; am++) {
                const int row_a = wm + am * 16 + ((lane >> 3) & 1) * 8 + (lane & 7);
                const int kcol  = k16 * 16 + ((lane >> 4) & 1) * 8;
                const uint32_t off = SW128((uint32_t)(row_a * 128 + kcol * 2));
                uint32_t ah[4], al[4];
                LDSM_X4(ah, ahi_base + off);
                LDSM_X4(al, alo_base + off);
#pragma unroll
                for (int an = 0; an < 4; an++) {
                    MMA_BF16(acc[am][an], ah, bh[an*2], bh[an*2+1]);
                    MMA_BF16(acc[am][an], ah, bl[an*2], bl[an*2+1]);
                    MMA_BF16(acc[am][an], al, bh[an*2], bh[an*2+1]);
                }
            }
        }
        // no trailing sync: next iteration writes the other buffers
    }

    // ---- epilogue ----
    const int g = lane >> 2;
    const int t = lane & 3;
#pragma unroll
    for (int am = 0; am < 4; am++) {
#pragma unroll
        for (int an = 0; an < 4; an++) {
            const int c  = wn + an * 8 + t * 2;
            const int r0 = block_m + wm + am * 16 + g;
            const int r1 = r0 + 8;
            if (r0 < M) {
                float2 v = make_float2(acc[am][an][0], acc[am][an][1]);
                *reinterpret_cast<float2*>(seq + (size_t)r0 * D_OUT + c) = v;
            }
            if (r1 < M) {
                float2 v = make_float2(acc[am][an][2], acc[am][an][3]);
                *reinterpret_cast<float2*>(seq + (size_t)r1 * D_OUT + c) = v;
            }
        }
    }
}

// ===========================================================================
// CSR build
// ===========================================================================
__global__ void zero_counts_kernel(int n)
{
    int i = blockIdx.x * blockDim.x + threadIdx.x;
    if (i < n) g_counts[i] = 0;
}

__global__ void hist_kernel(const int* __restrict__ edge_row, int E)
{
    int i = blockIdx.x * blockDim.x + threadIdx.x;
    if (i < E) atomicAdd(&g_counts[edge_row[i]], 1);
}

__global__ __launch_bounds__(1024) void block_sum_kernel(int n)
{
    int gid = blockIdx.x * 1024 + threadIdx.x;
    int c = (gid < n) ? g_counts[gid] : 0;
    const int lane = threadIdx.x & 31, w = threadIdx.x >> 5;
#pragma unroll
    for (int o = 16; o > 0; o >>= 1) c += __shfl_down_sync(0xFFFFFFFFu, c, o);
    __shared__ int ws[32];
    if (lane == 0) ws[w] = c;
    __syncthreads();
    if (w == 0) {
        int v = ws[lane];
#pragma unroll
        for (int o = 16; o > 0; o >>= 1) v += __shfl_down_sync(0xFFFFFFFFu, v, o);
        if (lane == 0) g_bsum[blockIdx.x] = v;
    }
}

__global__ void bsum_scan_kernel(int nb, int n)
{
    const int tid = threadIdx.x;                 // 64 threads
    int v = (tid < nb) ? g_bsum[tid] : 0;
    const int lane = tid & 31, w = tid >> 5;
    int x = v;
#pragma unroll
    for (int o = 1; o < 32; o <<= 1) {
        int y = __shfl_up_sync(0xFFFFFFFFu, x, o);
        if (lane >= o) x += y;
    }
    __shared__ int ws[2];
    if (lane == 31) ws[w] = x;
    __syncthreads();
    if (w == 1) x += ws[0];
    if (tid < nb) g_boff[tid] = x - v;
    if (tid == nb - 1) g_row_start[n] = x;
}

__global__ __launch_bounds__(1024) void scan_pass3_kernel(int n)
{
    int gid = blockIdx.x * 1024 + threadIdx.x;
    int c = (gid < n) ? g_counts[gid] : 0;
    const int lane = threadIdx.x & 31, w = threadIdx.x >> 5;
    int x = c;
#pragma unroll
    for (int o = 1; o < 32; o <<= 1) {
        int y = __shfl_up_sync(0xFFFFFFFFu, x, o);
        if (lane >= o) x += y;
    }
    __shared__ int ws[32];
    if (lane == 31) ws[w] = x;
    __syncthreads();
    if (w == 0) {
        int y = ws[lane];
#pragma unroll
        for (int o = 1; o < 32; o <<= 1) {
            int z = __shfl_up_sync(0xFFFFFFFFu, y, o);
            if (lane >= o) y += z;
        }
        ws[lane] = y;
    }
    __syncthreads();
    int excl = x - c + (w ? ws[w - 1] : 0) + g_boff[blockIdx.x];
    if (gid < n) { g_row_start[gid] = excl; g_cursor[gid] = excl; }
}

__global__ void bucket_kernel(const float* __restrict__ edge_val,
                              const int*   __restrict__ edge_row,
                              const int*   __restrict__ edge_col, int E)
{
    int i = blockIdx.x * blockDim.x + threadIdx.x;
    if (i >= E) return;
    int r = edge_row[i];
    int pos = atomicAdd(&g_cursor[r], 1);
    g_sorted[pos] = make_int2(edge_col[i], __float_as_int(edge_val[i]));
}

// ===========================================================================
// Gather: one warp per row; fused bias + PReLU; 4-way ILP; packed edges
// ===========================================================================
__global__ __launch_bounds__(256) void gather_kernel(
    const float* __restrict__ seq,
    const float* __restrict__ bias,
    const float* __restrict__ alpha,
    float* __restrict__ out, int n_nodes)
{
    int w = blockIdx.x * (blockDim.x >> 5) + (threadIdx.x >> 5);
    if (w >= n_nodes) return;
    const int lane = threadIdx.x & 31;

    const int s = g_row_start[w];
    const int e = g_row_start[w + 1];

    float4 acc = make_float4(0.f, 0.f, 0.f, 0.f);
    int i = s;
    for (; i + 3 < e; i += 4) {
        int2 p0 = g_sorted[i],   p1 = g_sorted[i+1];
        int2 p2 = g_sorted[i+2], p3 = g_sorted[i+3];
        float4 s0 = *reinterpret_cast<const float4*>(seq + (size_t)p0.x * D_OUT + lane * 4);
        float4 s1 = *reinterpret_cast<const float4*>(seq + (size_t)p1.x * D_OUT + lane * 4);
        float4 s2 = *reinterpret_cast<const float4*>(seq + (size_t)p2.x * D_OUT + lane * 4);
        float4 s3 = *reinterpret_cast<const float4*>(seq + (size_t)p3.x * D_OUT + lane * 4);
        float v0 = __int_as_float(p0.y), v1 = __int_as_float(p1.y);
        float v2 = __int_as_float(p2.y), v3 = __int_as_float(p3.y);
        acc.x = fmaf(v0, s0.x, acc.x); acc.y = fmaf(v0, s0.y, acc.y);
        acc.z = fmaf(v0, s0.z, acc.z); acc.w = fmaf(v0, s0.w, acc.w);
        acc.x = fmaf(v1, s1.x, acc.x); acc.y = fmaf(v1, s1.y, acc.y);
        acc.z = fmaf(v1, s1.z, acc.z); acc.w = fmaf(v1, s1.w, acc.w);
        acc.x = fmaf(v2, s2.x, acc.x); acc.y = fmaf(v2, s2.y, acc.y);
        acc.z = fmaf(v2, s2.z, acc.z); acc.w = fmaf(v2, s2.w, acc.w);
        acc.x = fmaf(v3, s3.x, acc.x); acc.y = fmaf(v3, s3.y, acc.y);
        acc.z = fmaf(v3, s3.z, acc.z); acc.w = fmaf(v3, s3.w, acc.w);
    }
    for (; i < e; i++) {
        int2 p = g_sorted[i];
        float v = __int_as_float(p.y);
        float4 sv = *reinterpret_cast<const float4*>(seq + (size_t)p.x * D_OUT + lane * 4);
        acc.x = fmaf(v, sv.x, acc.x); acc.y = fmaf(v, sv.y, acc.y);
        acc.z = fmaf(v, sv.z, acc.z); acc.w = fmaf(v, sv.w, acc.w);
    }

    const float a = alpha[0];
    float4 b = *reinterpret_cast<const float4*>(bias + lane * 4);
    acc.x += b.x; acc.y += b.y; acc.z += b.z; acc.w += b.w;
    acc.x = acc.x > 0.f ? acc.x : a * acc.x;
    acc.y = acc.y > 0.f ? acc.y : a * acc.y;
    acc.z = acc.z > 0.f ? acc.z : a * acc.z;
    acc.w = acc.w > 0.f ? acc.w : a * acc.w;

    *reinterpret_cast<float4*>(out + (size_t)w * D_OUT + lane * 4) = acc;
}

// ===========================================================================
extern "C" void kernel_launch(void* const* d_in, const int* in_sizes, int n_in,
                              void* d_out, int out_size)
{
    const float* x        = (const float*)d_in[0];
    const float* weight   = (const float*)d_in[1];
    const float* bias     = (const float*)d_in[2];
    const float* alpha    = (const float*)d_in[3];
    const float* edge_val = (const float*)d_in[4];
    const int*   edge_row = (const int*)d_in[5];
    const int*   edge_col = (const int*)d_in[6];
    float*       out      = (float*)d_out;

    const int n_nodes = in_sizes[0] / D_IN;     // 40000
    const int n_edges = in_sizes[4];            // 640000

    float* seq = nullptr;
    cudaGetSymbolAddress((void**)&seq, g_seq);

    static cudaStream_t s2 = nullptr;
    static cudaEvent_t evA = nullptr, evB = nullptr;
    static bool init_done = false;
    if (!init_done) {
        cudaStreamCreateWithFlags(&s2, cudaStreamNonBlocking);
        cudaEventCreateWithFlags(&evA, cudaEventDisableTiming);
        cudaEventCreateWithFlags(&evB, cudaEventDisableTiming);
        cudaFuncSetAttribute(gemm_mma_kernel,
                             cudaFuncAttributeMaxDynamicSharedMemorySize, SM_TOTAL);
        init_done = true;
    }

    // fork: CSR build on s2 runs concurrently with GEMM on the main stream
    cudaEventRecord(evA, 0);
    cudaStreamWaitEvent(s2, evA, 0);

    // --- main stream: W prep + GEMM ---
    prep_w_kernel<<<(D_OUT * D_IN + 255) / 256, 256>>>(weight);
    gemm_mma_kernel<<<(n_nodes + 127) / 128, 256, SM_TOTAL>>>(x, seq, n_nodes);

    // --- s2: CSR build ---
    zero_counts_kernel<<<(n_nodes + 255) / 256, 256, 0, s2>>>(n_nodes);
    hist_kernel<<<(n_edges + 255) / 256, 256, 0, s2>>>(edge_row, n_edges);
    {
        int nb = (n_nodes + 1023) / 1024;
        block_sum_kernel<<<nb, 1024, 0, s2>>>(n_nodes);
        bsum_scan_kernel<<<1, 64, 0, s2>>>(nb, n_nodes);
        scan_pass3_kernel<<<nb, 1024, 0, s2>>>(n_nodes);
    }
    bucket_kernel<<<(n_edges + 255) / 256, 256, 0, s2>>>(edge_val, edge_row, edge_col, n_edges);
    cudaEventRecord(evB, s2);

    // join, then gather
    cudaStreamWaitEvent(0, evB, 0);
    {
        int warps_per_block = 256 / 32;
        int grid = (n_nodes + warps_per_block - 1) / warps_per_block;
        gather_kernel<<<grid, 256>>>(seq, bias, alpha, out, n_nodes);
    }
}

// round 9
// speedup vs baseline: 3.8973x; 1.0057x over previous
#include <cuda_runtime.h>
#include <cuda_bf16.h>
#include <cuda_fp16.h>
#include <cstdint>

// GraphConvolution: out = PReLU( A_coo @ (X @ W^T) + bias )
//   x[40000,512] f32, weight[128,512] f32, bias[128], alpha[1],
//   edge_val[640000] f32, edge_row/col[640000] i32 -> out[40000,128] f32

#define D_IN   512
#define D_OUT  128
#define MAX_NODES 40000
#define MAX_EDGES 640000
#define SCAN_BLOCKS ((MAX_NODES + 1023) / 1024)

// Scratch (device globals: allocation-free rule)
__device__ __half g_seq_h[(size_t)MAX_NODES * D_OUT];   // fp16 seq (10.24 MB)
__device__ int   g_counts[MAX_NODES];
__device__ int   g_row_start[MAX_NODES + 1];
__device__ int   g_cursor[MAX_NODES];
__device__ int2  g_sorted[MAX_EDGES];          // (col, val-bits) packed
__device__ int   g_bsum[SCAN_BLOCKS];
__device__ int   g_boff[SCAN_BLOCKS];
__device__ __nv_bfloat16 g_whi[D_OUT * D_IN];  // pre-split weight hi
__device__ __nv_bfloat16 g_wlo[D_OUT * D_IN];  // pre-split weight lo

// ===========================================================================
// Helpers (base-ISA PTX only; must compile at .target sm_103)
// ===========================================================================
__device__ __forceinline__ uint32_t smem_to_u32(const void* p) {
    uint32_t a;
    asm("{ .reg .u64 t; cvta.to.shared.u64 t, %1; cvt.u32.u64 %0, t; }"
        : "=r"(a) : "l"(p));
    return a;
}

#define LDSM_X4(r, addr) \
    asm volatile("ldmatrix.sync.aligned.m8n8.x4.shared.b16 {%0,%1,%2,%3}, [%4];" \
        : "=r"((r)[0]), "=r"((r)[1]), "=r"((r)[2]), "=r"((r)[3]) : "r"(addr))

#define MMA_BF16(d, a, b0, b1) \
    asm volatile("mma.sync.aligned.m16n8k16.row.col.f32.bf16.bf16.f32 " \
        "{%0,%1,%2,%3}, {%4,%5,%6,%7}, {%8,%9}, {%0,%1,%2,%3};" \
        : "+f"((d)[0]), "+f"((d)[1]), "+f"((d)[2]), "+f"((d)[3]) \
        : "r"((a)[0]), "r"((a)[1]), "r"((a)[2]), "r"((a)[3]), "r"(b0), "r"(b1))

#define STS128(addr, r0, r1, r2, r3) \
    asm volatile("st.shared.v4.b32 [%0], {%1, %2, %3, %4};" \
        :: "r"(addr), "r"(r0), "r"(r1), "r"(r2), "r"(r3) : "memory")

#define CP_ASYNC16(dst, src) \
    asm volatile("cp.async.cg.shared.global [%0], [%1], 16;" \
        :: "r"(dst), "l"(src) : "memory")
#define CP_COMMIT() asm volatile("cp.async.commit_group;" ::: "memory")
#define CP_WAIT0()  asm volatile("cp.async.wait_group 0;" ::: "memory")

// 128-byte-row swizzle: bits[6:4] ^= bits[9:7]
#define SW128(off) ((off) ^ (((off) >> 3) & 0x70))

// Fast split: hi = truncate-to-bf16, lo = a - hi (exact), pack via PRMT/cvt.
__device__ __forceinline__ void split8_fast(const float* f, uint32_t* hi, uint32_t* lo) {
#pragma unroll
    for (int q = 0; q < 4; q++) {
        float a = f[2*q], b = f[2*q+1];
        uint32_t ua = __float_as_uint(a), ub = __float_as_uint(b);
        hi[q] = __byte_perm(ua, ub, 0x7632);
        float ha = __uint_as_float(ua & 0xFFFF0000u);
        float hb = __uint_as_float(ub & 0xFFFF0000u);
        __nv_bfloat162 l2 = __float22bfloat162_rn(make_float2(a - ha, b - hb));
        lo[q] = *reinterpret_cast<uint32_t*>(&l2);
    }
}

// ===========================================================================
// W prep: split weight into bf16 hi/lo once
// ===========================================================================
__global__ void prep_w_kernel(const float* __restrict__ W)
{
    int i = blockIdx.x * blockDim.x + threadIdx.x;
    if (i < D_OUT * D_IN) {
        float w = W[i];
        __nv_bfloat16 h = __float2bfloat16(w);
        g_whi[i] = h;
        g_wlo[i] = __float2bfloat16(w - __bfloat162float(h));
    }
}

// smem layout (bytes): A[stage][hi|lo] then B[stage][hi|lo], 16KB tiles
#define SM_A 0
#define SM_B 65536
#define SM_TOTAL 131072

// ===========================================================================
// GEMM: seq_h[M,128] = fp16(X[M,512] @ W^T) via bf16 split-2 HMMA
// ===========================================================================
__global__ __launch_bounds__(256) void gemm_mma_kernel(
    const float* __restrict__ X, int M)
{
    extern __shared__ char smem[];
    const uint32_t sb = smem_to_u32(smem);
    const int tid  = threadIdx.x;
    const int lane = tid & 31;
    const int wid  = tid >> 5;
    const int block_m = blockIdx.x * 128;

    const int lrow = tid & 127;
    const int lcol = (tid >> 7) * 32;
    const int a_row = block_m + lrow;
    const bool a_ok = (a_row < M);

    const int wm = (wid & 1) * 64;
    const int wn = (wid >> 1) * 32;

    float acc[4][4][4];
#pragma unroll
    for (int i = 0; i < 4; i++)
#pragma unroll
        for (int j = 0; j < 4; j++)
#pragma unroll
            for (int q = 0; q < 4; q++) acc[i][j][q] = 0.f;

    float4 afa[8];

    auto load_a = [&](int ch) {
        const int k0 = ch * 64;
#pragma unroll
        for (int j = 0; j < 4; j++) {
            if (a_ok) {
                const float* p = X + (size_t)a_row * D_IN + k0 + lcol + j * 8;
                afa[2*j]   = *reinterpret_cast<const float4*>(p);
                afa[2*j+1] = *reinterpret_cast<const float4*>(p + 4);
            } else {
                afa[2*j] = afa[2*j+1] = make_float4(0.f, 0.f, 0.f, 0.f);
            }
        }
    };

    auto store_a = [&](int st) {
        const uint32_t ahi = sb + SM_A + st * 32768;
        const uint32_t alo = ahi + 16384;
#pragma unroll
        for (int j = 0; j < 4; j++) {
            const int col = lcol + j * 8;
            const uint32_t off = SW128((uint32_t)(lrow * 128 + col * 2));
            float f[8] = {afa[2*j].x, afa[2*j].y, afa[2*j].z, afa[2*j].w,
                          afa[2*j+1].x, afa[2*j+1].y, afa[2*j+1].z, afa[2*j+1].w};
            uint32_t hi[4], lo[4];
            split8_fast(f, hi, lo);
            STS128(ahi + off, hi[0], hi[1], hi[2], hi[3]);
            STS128(alo + off, lo[0], lo[1], lo[2], lo[3]);
        }
    };

    auto load_b = [&](int ch, int st) {
        const int k0 = ch * 64;
        const uint32_t bhi = sb + SM_B + st * 32768;
        const uint32_t blo = bhi + 16384;
#pragma unroll
        for (int it = 0; it < 4; it++) {
            int idx = it * 256 + tid;
            int row = idx >> 3;
            int seg = idx & 7;
            uint32_t off = SW128((uint32_t)(row * 128 + seg * 16));
            CP_ASYNC16(bhi + off, g_whi + (size_t)row * D_IN + k0 + seg * 8);
            CP_ASYNC16(blo + off, g_wlo + (size_t)row * D_IN + k0 + seg * 8);
        }
        CP_COMMIT();
    };

    load_a(0);
    load_b(0, 0);

    for (int ch = 0; ch < 8; ch++) {
        const int st = ch & 1;

        store_a(st);
        if (ch < 7) load_a(ch + 1);

        CP_WAIT0();
        __syncthreads();

        if (ch < 7) load_b(ch + 1, st ^ 1);

        const uint32_t ahi_base = sb + SM_A + st * 32768;
        const uint32_t alo_base = ahi_base + 16384;
        const uint32_t bhi_base = sb + SM_B + st * 32768;
        const uint32_t blo_base = bhi_base + 16384;

#pragma unroll
        for (int k16 = 0; k16 < 4; k16++) {
            uint32_t bh[8], bl[8];
#pragma unroll
            for (int h = 0; h < 2; h++) {
                const int row_b = wn + h * 16 + ((lane >> 4) & 1) * 8 + (lane & 7);
                const int kcol  = k16 * 16 + ((lane >> 3) & 1) * 8;
                const uint32_t off = SW128((uint32_t)(row_b * 128 + kcol * 2));
                LDSM_X4(&bh[h * 4], bhi_base + off);
                LDSM_X4(&bl[h * 4], blo_base + off);
            }
#pragma unroll
            for (int am = 0; am < 4; am++) {
                const int row_a = wm + am * 16 + ((lane >> 3) & 1) * 8 + (lane & 7);
                const int kcol  = k16 * 16 + ((lane >> 4) & 1) * 8;
                const uint32_t off = SW128((uint32_t)(row_a * 128 + kcol * 2));
                uint32_t ah[4], al[4];
                LDSM_X4(ah, ahi_base + off);
                LDSM_X4(al, alo_base + off);
#pragma unroll
                for (int an = 0; an < 4; an++) {
                    MMA_BF16(acc[am][an], ah, bh[an*2], bh[an*2+1]);
                    MMA_BF16(acc[am][an], ah, bl[an*2], bl[an*2+1]);
                    MMA_BF16(acc[am][an], al, bh[an*2], bh[an*2+1]);
                }
            }
        }
    }

    // ---- epilogue: f32 acc -> fp16 seq ----
    const int g = lane >> 2;
    const int t = lane & 3;
#pragma unroll
    for (int am = 0; am < 4; am++) {
#pragma unroll
        for (int an = 0; an < 4; an++) {
            const int c  = wn + an * 8 + t * 2;
            const int r0 = block_m + wm + am * 16 + g;
            const int r1 = r0 + 8;
            if (r0 < M) {
                __half2 v = __float22half2_rn(make_float2(acc[am][an][0], acc[am][an][1]));
                *reinterpret_cast<__half2*>(g_seq_h + (size_t)r0 * D_OUT + c) = v;
            }
            if (r1 < M) {
                __half2 v = __float22half2_rn(make_float2(acc[am][an][2], acc[am][an][3]));
                *reinterpret_cast<__half2*>(g_seq_h + (size_t)r1 * D_OUT + c) = v;
            }
        }
    }
}

// ===========================================================================
// CSR build
// ===========================================================================
__global__ void zero_counts_kernel(int n)
{
    int i = blockIdx.x * blockDim.x + threadIdx.x;
    if (i < n) g_counts[i] = 0;
}

__global__ void hist_kernel(const int* __restrict__ edge_row, int E)
{
    int i = blockIdx.x * blockDim.x + threadIdx.x;
    if (i < E) atomicAdd(&g_counts[edge_row[i]], 1);
}

__global__ __launch_bounds__(1024) void block_sum_kernel(int n)
{
    int gid = blockIdx.x * 1024 + threadIdx.x;
    int c = (gid < n) ? g_counts[gid] : 0;
    const int lane = threadIdx.x & 31, w = threadIdx.x >> 5;
#pragma unroll
    for (int o = 16; o > 0; o >>= 1) c += __shfl_down_sync(0xFFFFFFFFu, c, o);
    __shared__ int ws[32];
    if (lane == 0) ws[w] = c;
    __syncthreads();
    if (w == 0) {
        int v = ws[lane];
#pragma unroll
        for (int o = 16; o > 0; o >>= 1) v += __shfl_down_sync(0xFFFFFFFFu, v, o);
        if (lane == 0) g_bsum[blockIdx.x] = v;
    }
}

__global__ void bsum_scan_kernel(int nb, int n)
{
    const int tid = threadIdx.x;                 // 64 threads
    int v = (tid < nb) ? g_bsum[tid] : 0;
    const int lane = tid & 31, w = tid >> 5;
    int x = v;
#pragma unroll
    for (int o = 1; o < 32; o <<= 1) {
        int y = __shfl_up_sync(0xFFFFFFFFu, x, o);
        if (lane >= o) x += y;
    }
    __shared__ int ws[2];
    if (lane == 31) ws[w] = x;
    __syncthreads();
    if (w == 1) x += ws[0];
    if (tid < nb) g_boff[tid] = x - v;
    if (tid == nb - 1) g_row_start[n] = x;
}

__global__ __launch_bounds__(1024) void scan_pass3_kernel(int n)
{
    int gid = blockIdx.x * 1024 + threadIdx.x;
    int c = (gid < n) ? g_counts[gid] : 0;
    const int lane = threadIdx.x & 31, w = threadIdx.x >> 5;
    int x = c;
#pragma unroll
    for (int o = 1; o < 32; o <<= 1) {
        int y = __shfl_up_sync(0xFFFFFFFFu, x, o);
        if (lane >= o) x += y;
    }
    __shared__ int ws[32];
    if (lane == 31) ws[w] = x;
    __syncthreads();
    if (w == 0) {
        int y = ws[lane];
#pragma unroll
        for (int o = 1; o < 32; o <<= 1) {
            int z = __shfl_up_sync(0xFFFFFFFFu, y, o);
            if (lane >= o) y += z;
        }
        ws[lane] = y;
    }
    __syncthreads();
    int excl = x - c + (w ? ws[w - 1] : 0) + g_boff[blockIdx.x];
    if (gid < n) { g_row_start[gid] = excl; g_cursor[gid] = excl; }
}

__global__ void bucket_kernel(const float* __restrict__ edge_val,
                              const int*   __restrict__ edge_row,
                              const int*   __restrict__ edge_col, int E)
{
    int i = blockIdx.x * blockDim.x + threadIdx.x;
    if (i >= E) return;
    int r = edge_row[i];
    int pos = atomicAdd(&g_cursor[r], 1);
    g_sorted[pos] = make_int2(edge_col[i], __float_as_int(edge_val[i]));
}

// ===========================================================================
// Gather: one warp per row; fp16 seq reads; f32 accumulate; bias + PReLU
// ===========================================================================
__device__ __forceinline__ void gacc(float4& acc, float v, uint2 raw) {
    __half2 h0 = *reinterpret_cast<__half2*>(&raw.x);
    __half2 h1 = *reinterpret_cast<__half2*>(&raw.y);
    float2 f0 = __half22float2(h0);
    float2 f1 = __half22float2(h1);
    acc.x = fmaf(v, f0.x, acc.x); acc.y = fmaf(v, f0.y, acc.y);
    acc.z = fmaf(v, f1.x, acc.z); acc.w = fmaf(v, f1.y, acc.w);
}

__global__ __launch_bounds__(256) void gather_kernel(
    const float* __restrict__ bias,
    const float* __restrict__ alpha,
    float* __restrict__ out, int n_nodes)
{
    int w = blockIdx.x * (blockDim.x >> 5) + (threadIdx.x >> 5);
    if (w >= n_nodes) return;
    const int lane = threadIdx.x & 31;

    const int s = g_row_start[w];
    const int e = g_row_start[w + 1];

    float4 acc = make_float4(0.f, 0.f, 0.f, 0.f);
    int i = s;
    for (; i + 3 < e; i += 4) {
        int2 p0 = g_sorted[i],   p1 = g_sorted[i+1];
        int2 p2 = g_sorted[i+2], p3 = g_sorted[i+3];
        uint2 r0 = *reinterpret_cast<const uint2*>(g_seq_h + (size_t)p0.x * D_OUT + lane * 4);
        uint2 r1 = *reinterpret_cast<const uint2*>(g_seq_h + (size_t)p1.x * D_OUT + lane * 4);
        uint2 r2 = *reinterpret_cast<const uint2*>(g_seq_h + (size_t)p2.x * D_OUT + lane * 4);
        uint2 r3 = *reinterpret_cast<const uint2*>(g_seq_h + (size_t)p3.x * D_OUT + lane * 4);
        gacc(acc, __int_as_float(p0.y), r0);
        gacc(acc, __int_as_float(p1.y), r1);
        gacc(acc, __int_as_float(p2.y), r2);
        gacc(acc, __int_as_float(p3.y), r3);
    }
    for (; i < e; i++) {
        int2 p = g_sorted[i];
        uint2 r = *reinterpret_cast<const uint2*>(g_seq_h + (size_t)p.x * D_OUT + lane * 4);
        gacc(acc, __int_as_float(p.y), r);
    }

    const float a = alpha[0];
    float4 b = *reinterpret_cast<const float4*>(bias + lane * 4);
    acc.x += b.x; acc.y += b.y; acc.z += b.z; acc.w += b.w;
    acc.x = acc.x > 0.f ? acc.x : a * acc.x;
    acc.y = acc.y > 0.f ? acc.y : a * acc.y;
    acc.z = acc.z > 0.f ? acc.z : a * acc.z;
    acc.w = acc.w > 0.f ? acc.w : a * acc.w;

    *reinterpret_cast<float4*>(out + (size_t)w * D_OUT + lane * 4) = acc;
}

// ===========================================================================
extern "C" void kernel_launch(void* const* d_in, const int* in_sizes, int n_in,
                              void* d_out, int out_size)
{
    const float* x        = (const float*)d_in[0];
    const float* weight   = (const float*)d_in[1];
    const float* bias     = (const float*)d_in[2];
    const float* alpha    = (const float*)d_in[3];
    const float* edge_val = (const float*)d_in[4];
    const int*   edge_row = (const int*)d_in[5];
    const int*   edge_col = (const int*)d_in[6];
    float*       out      = (float*)d_out;

    const int n_nodes = in_sizes[0] / D_IN;     // 40000
    const int n_edges = in_sizes[4];            // 640000

    static cudaStream_t s2 = nullptr;
    static cudaEvent_t evA = nullptr, evB = nullptr;
    static bool init_done = false;
    if (!init_done) {
        cudaStreamCreateWithFlags(&s2, cudaStreamNonBlocking);
        cudaEventCreateWithFlags(&evA, cudaEventDisableTiming);
        cudaEventCreateWithFlags(&evB, cudaEventDisableTiming);
        cudaFuncSetAttribute(gemm_mma_kernel,
                             cudaFuncAttributeMaxDynamicSharedMemorySize, SM_TOTAL);
        init_done = true;
    }

    // fork: CSR build on s2 runs concurrently with GEMM on the main stream
    cudaEventRecord(evA, 0);
    cudaStreamWaitEvent(s2, evA, 0);

    // --- main stream: W prep + GEMM ---
    prep_w_kernel<<<(D_OUT * D_IN + 255) / 256, 256>>>(weight);
    gemm_mma_kernel<<<(n_nodes + 127) / 128, 256, SM_TOTAL>>>(x, n_nodes);

    // --- s2: CSR build ---
    zero_counts_kernel<<<(n_nodes + 255) / 256, 256, 0, s2>>>(n_nodes);
    hist_kernel<<<(n_edges + 255) / 256, 256, 0, s2>>>(edge_row, n_edges);
    {
        int nb = (n_nodes + 1023) / 1024;
        block_sum_kernel<<<nb, 1024, 0, s2>>>(n_nodes);
        bsum_scan_kernel<<<1, 64, 0, s2>>>(nb, n_nodes);
        scan_pass3_kernel<<<nb, 1024, 0, s2>>>(n_nodes);
    }
    bucket_kernel<<<(n_edges + 255) / 256, 256, 0, s2>>>(edge_val, edge_row, edge_col, n_edges);
    cudaEventRecord(evB, s2);

    // join, then gather
    cudaStreamWaitEvent(0, evB, 0);
    {
        int warps_per_block = 256 / 32;
        int grid = (n_nodes + warps_per_block - 1) / warps_per_block;
        gather_kernel<<<grid, 256>>>(bias, alpha, out, n_nodes);
    }
}